// round 11
// baseline (speedup 1.0000x reference)
#include <cuda_runtime.h>
#include <cuda_fp16.h>
#include <cstdint>

#define L    16
#define NB   128
#define NC   128
#define NE   10
#define NT3  816
#define NT3P 832      // padded to 13*64
#define NT2  136
#define COLS2 24
#define NWY  68
#define NCHUNK 13     // K chunks of 64

typedef unsigned long long ull;

// ---------------- device globals ----------------
__device__ unsigned g_idx3[NT3];
__device__ unsigned g_idx2[NT2];
__device__ float    g_Us2[NT2 * COLS2];
__device__ float    g_Us1[L * 4];
__device__ float    g_wy[NB * NWY * NC];
// split-fp16 coefficient chunk images, row-major: [chunk][j=128][t_in=64]
__device__ __align__(16) __half g_B3hi[NCHUNK * 8192];
__device__ __align__(16) __half g_B3lo[NCHUNK * 8192];

// ---------------- helpers ----------------
__device__ __forceinline__ uint32_t smem_u32(const void* p) {
    uint32_t a;
    asm("{ .reg .u64 t; cvta.to.shared.u64 t, %1; cvt.u32.u64 %0, t; }" : "=r"(a) : "l"(p));
    return a;
}
__device__ __forceinline__ ull pack2(float v) {
    ull r; asm("mov.b64 %0, {%1, %1};" : "=l"(r) : "f"(v)); return r;
}
__device__ __forceinline__ void unpack2(ull v, float& lo, float& hi) {
    asm("mov.b64 {%0, %1}, %2;" : "=f"(lo), "=f"(hi) : "l"(v));
}
__device__ __forceinline__ void fma2(ull& d, ull a, ull b) {
    asm("fma.rn.f32x2 %0, %1, %2, %0;" : "+l"(d) : "l"(a), "l"(b));
}
__device__ __forceinline__ void ldsm4(uint32_t* r, uint32_t addr) {
    asm volatile("ldmatrix.sync.aligned.m8n8.x4.shared.b16 {%0,%1,%2,%3}, [%4];"
                 : "=r"(r[0]), "=r"(r[1]), "=r"(r[2]), "=r"(r[3]) : "r"(addr));
}
__device__ __forceinline__ void mma16816h(float* d, const uint32_t* a,
                                          uint32_t b0, uint32_t b1) {
    asm volatile("mma.sync.aligned.m16n8k16.row.col.f32.f16.f16.f32 "
                 "{%0,%1,%2,%3}, {%4,%5,%6,%7}, {%8,%9}, {%0,%1,%2,%3};"
                 : "+f"(d[0]), "+f"(d[1]), "+f"(d[2]), "+f"(d[3])
                 : "r"(a[0]), "r"(a[1]), "r"(a[2]), "r"(a[3]), "r"(b0), "r"(b1));
}
__device__ __forceinline__ void cp16(uint32_t daddr, const void* gsrc) {
    asm volatile("cp.async.cg.shared.global [%0], [%1], 16;"
                 :: "r"(daddr), "l"(gsrc) : "memory");
}
#define CP_COMMIT() asm volatile("cp.async.commit_group;" ::: "memory")
#define CP_WAIT0()  asm volatile("cp.async.wait_group 0;" ::: "memory")

// ---------------- K0: symmetrize + fp16-split (regridded) ----------------
// grid = 130 x 256: blocks 0..127 -> order-3 items; 128 -> pairs; 129 -> order-1
__global__ void __launch_bounds__(256) k_setup(
        const float* __restrict__ U1_0e, const float* __restrict__ U2_0e,
        const float* __restrict__ U3_0e, const float* __restrict__ U1_1o,
        const float* __restrict__ U2_1o, const float* __restrict__ U3_1o) {
    const int blk = blockIdx.x;
    const int tid = threadIdx.x;
    if (blk < 128) {
#pragma unroll
        for (int it = 0; it < 4; ++it) {
            int item = blk * 832 + it * 256 + tid;
            if (item >= (blk + 1) * 832) break;
            int t = item >> 7;
            int j = item & 127;
            float val = 0.f;
            if (t < NT3) {
                int rem = t, A = 0, B = 0, D = 0;
                {
                    int i = 0;
                    for (;;) { int m = L - i; int cnt = m * (m + 1) / 2;
                               if (rem < cnt) break; rem -= cnt; i++; }
                    A = i;
                    int q = A;
                    for (;;) { int cnt = L - q;
                               if (rem < cnt) break; rem -= cnt; q++; }
                    B = q; D = B + rem;
                }
                if (j == 0) g_idx3[t] = (unsigned)A | ((unsigned)B << 8) | ((unsigned)D << 16);
                int P[6][3] = {{A,B,D},{A,D,B},{B,A,D},{B,D,A},{D,A,B},{D,B,A}};
                if (j < 122) {
                    for (int i = 0; i < 6; i++) {
                        bool dup = false;
                        for (int q = 0; q < i; q++)
                            if (P[q][0] == P[i][0] && P[q][1] == P[i][1] && P[q][2] == P[i][2]) dup = true;
                        if (dup) continue;
                        int p0 = P[i][0], p1 = P[i][1], p2 = P[i][2];
                        if (j < 23) {
                            val += U3_0e[((p0 * L + p1) * L + p2) * 23 + j];
                        } else {
                            int w = (j - 23) / 33, k = (j - 23) % 33;
                            val += U3_1o[(((w * L + p0) * L + p1) * L + p2) * 33 + k];
                        }
                    }
                }
            }
            __half hv = __float2half_rn(val);
            __half lv = __float2half_rn(val - __half2float(hv));
            int chunk = t >> 6, t_in = t & 63;
            g_B3hi[chunk * 8192 + j * 64 + t_in] = hv;
            g_B3lo[chunk * 8192 + j * 64 + t_in] = lv;
        }
    } else if (blk == 128) {
        for (int i = tid; i < NT2 * COLS2; i += 256) {
            int t = i / COLS2, j = i - t * COLS2;
            int rem = t, A = 0, B = 0;
            {
                int k = 0;
                for (;;) { int cnt = L - k;
                           if (rem < cnt) break; rem -= cnt; k++; }
                A = k; B = A + rem;
            }
            if (j == 0) g_idx2[t] = (unsigned)A | ((unsigned)B << 8);
            float val = 0.f;
            if (j < 22) {
                if (j < 4) {
                    val = U2_0e[(A * L + B) * 4 + j];
                    if (A != B) val += U2_0e[(B * L + A) * 4 + j];
                } else {
                    int w = (j - 4) / 6, k = (j - 4) % 6;
                    val = U2_1o[((w * L + A) * L + B) * 6 + k];
                    if (A != B) val += U2_1o[((w * L + B) * L + A) * 6 + k];
                }
            }
            g_Us2[t * COLS2 + j] = val;
        }
    } else {
        if (tid < L * 4) {
            int a = tid >> 2, col = tid & 3;
            g_Us1[a * 4 + col] = (col == 0) ? U1_0e[a] : U1_1o[(col - 1) * L + a];
        }
    }
}

// ---------------- K1: wy + order-1/2 + output base (unchanged, passing) ----
__global__ void __launch_bounds__(256) k_wy(
        const float* __restrict__ y, const float* __restrict__ x,
        const float* __restrict__ w3_0e, const float* __restrict__ w3_1o,
        const float* __restrict__ w2_0e, const float* __restrict__ w2_1o,
        const float* __restrict__ w1_0e, const float* __restrict__ w1_1o,
        float* __restrict__ out) {
    __shared__ __align__(16) float ys[NE];
    __shared__ __align__(16) float Xs[NC * 17];
    __shared__ __align__(16) float wys[12 * NC];
    __shared__ __align__(16) float Us2s[NT2 * COLS2];
    __shared__ __align__(16) float Us1s[L * 4];
    __shared__ __align__(16) float red2[NC * 4 * 2];
    const int tid = threadIdx.x;
    const int b = blockIdx.x;

    if (tid < NE) ys[tid] = y[b * NE + tid];
    if (tid < L * 4) Us1s[tid] = g_Us1[tid];
    {
        int c = tid >> 1, off = (tid & 1) * 8;
        const float4* xp = (const float4*)(x + (b * NC + c) * L + off);
        float4 v0 = xp[0], v1 = xp[1];
        float* dst = Xs + c * 17 + off;
        dst[0] = v0.x; dst[1] = v0.y; dst[2] = v0.z; dst[3] = v0.w;
        dst[4] = v1.x; dst[5] = v1.y; dst[6] = v1.z; dst[7] = v1.w;
    }
    for (int i = tid; i < NT2 * (COLS2 / 4); i += 256)
        ((float4*)Us2s)[i] = ((const float4*)g_Us2)[i];
    __syncthreads();

    for (int idx = tid; idx < NWY * NC; idx += 256) {
        int jw = idx >> 7, c = idx & 127;
        const float* wsrc; int K, k;
        if (jw < 23)       { wsrc = w3_0e; K = 23; k = jw; }
        else if (jw < 56)  { wsrc = w3_1o; K = 33; k = jw - 23; }
        else if (jw < 60)  { wsrc = w2_0e; K = 4;  k = jw - 56; }
        else if (jw < 66)  { wsrc = w2_1o; K = 6;  k = jw - 60; }
        else if (jw == 66) { wsrc = w1_0e; K = 1;  k = 0; }
        else               { wsrc = w1_1o; K = 1;  k = 0; }
        float acc = 0.f;
#pragma unroll
        for (int e = 0; e < NE; e++)
            acc = fmaf(wsrc[(e * K + k) * NC + c], ys[e], acc);
        g_wy[(b * NWY + jw) * NC + c] = acc;
        if (jw >= 56) wys[(jw - 56) * NC + c] = acc;
    }
    __syncthreads();

    const int c = tid & 127;
    const int half = tid >> 7;
    const float* Xc = Xs + c * 17;
    ull P2[11];
#pragma unroll
    for (int k = 0; k < 11; k++) P2[k] = 0ull;
    for (int t = half * 68; t < half * 68 + 68; t++) {
        unsigned u = g_idx2[t];
        ull m2 = pack2(Xc[u & 255] * Xc[(u >> 8) & 255]);
        const ull* row = (const ull*)(Us2s + t * COLS2);
#pragma unroll
        for (int k = 0; k < 11; k++) fma2(P2[k], m2, row[k]);
    }
    float contrib[4] = {0.f, 0.f, 0.f, 0.f};
#pragma unroll
    for (int k = 0; k < 11; k++) {
        float lo, hi;
        unpack2(P2[k], lo, hi);
#pragma unroll
        for (int hh = 0; hh < 2; hh++) {
            int j = 2 * k + hh;
            float v = (hh == 0) ? lo : hi;
            int tgt, row;
            if (j < 4) { tgt = 0; row = j; }
            else { int wq = (j - 4) / 6; tgt = 1 + wq; row = 4 + (j - 4 - wq * 6); }
            contrib[tgt] += v * wys[row * NC + c];
        }
    }
    if (half == 0) {
        float P0 = 0.f, P1 = 0.f, Pq = 0.f, P3 = 0.f;
#pragma unroll
        for (int a = 0; a < L; a++) {
            float xa = Xc[a];
            P0 = fmaf(Us1s[a * 4 + 0], xa, P0);
            P1 = fmaf(Us1s[a * 4 + 1], xa, P1);
            Pq = fmaf(Us1s[a * 4 + 2], xa, Pq);
            P3 = fmaf(Us1s[a * 4 + 3], xa, P3);
        }
        contrib[0] = fmaf(P0, wys[10 * NC + c], contrib[0]);
        contrib[1] = fmaf(P1, wys[11 * NC + c], contrib[1]);
        contrib[2] = fmaf(Pq, wys[11 * NC + c], contrib[2]);
        contrib[3] = fmaf(P3, wys[11 * NC + c], contrib[3]);
    }
#pragma unroll
    for (int tgt = 0; tgt < 4; tgt++)
        red2[(c * 4 + tgt) * 2 + half] = contrib[tgt];
    __syncthreads();
    for (int i = tid; i < 512; i += 256) {
        int cc = i >> 2, tgt = i & 3;
        float v = red2[i * 2] + red2[i * 2 + 1];
        if (tgt == 0) out[b * 512 + cc] = v;
        else out[b * 512 + 128 + 3 * cc + (tgt - 1)] = v;
    }
}

// ---------------- K2: order-3 HMMA fp16, fused build+MMA pipeline ----------
// grid = 256: (atom b, K-half kh). 8 warps = 4 row-groups x 2 col-groups.
// smem: A0 16K | A1 16K | B0 32K | B1 32K | Xs 8.5K | idx 3.3K  = ~110K
#define OFF_A0   0
#define OFF_A1   16384
#define OFF_B0   32768
#define OFF_B1   65536
#define OFF_XS   98304
#define OFF_IDX  107008
#define SMEM_TOTAL 110336

__global__ void __launch_bounds__(256, 2) k_main(const float* __restrict__ x,
                                                 float* __restrict__ out) {
    extern __shared__ __align__(1024) char smc[];
    const uint32_t sb = smem_u32(smc);
    const int tid = threadIdx.x;
    const int wid = tid >> 5;
    const int lane = tid & 31;
    const int b = blockIdx.x >> 1;
    const int kh = blockIdx.x & 1;
    const int q0 = kh ? 7 : 0;
    const int q1 = kh ? NCHUNK : 7;

    float* Xs = (float*)(smc + OFF_XS);
    unsigned* sIdx = (unsigned*)(smc + OFF_IDX);

    // prologue: stream B(q0), stage X + idx
    {
        const char* srcH = (const char*)g_B3hi + q0 * 16384;
        const char* srcL = (const char*)g_B3lo + q0 * 16384;
        for (int i = tid; i < 1024; i += 256) {
            int row = i >> 3, u = i & 7;
            uint32_t doff = (uint32_t)(row * 128 + ((u ^ (row & 7)) << 4));
            int soff = (row * 64 + u * 8) * 2;
            cp16(sb + OFF_B0 + doff, srcH + soff);
            cp16(sb + OFF_B0 + 16384 + doff, srcL + soff);
        }
        CP_COMMIT();
    }
    {
        int c = tid >> 1, off = (tid & 1) * 8;
        const float4* xp = (const float4*)(x + (b * NC + c) * L + off);
        float4 v0 = xp[0], v1 = xp[1];
        float* dst = Xs + c * 17 + off;
        dst[0] = v0.x; dst[1] = v0.y; dst[2] = v0.z; dst[3] = v0.w;
        dst[4] = v1.x; dst[5] = v1.y; dst[6] = v1.z; dst[7] = v1.w;
    }
    for (int i = tid; i < NT3; i += 256) sIdx[i] = g_idx3[i];
    __syncthreads();                       // Xs/idx ready for build

    // build A(q0) -> A0
    for (int item = tid; item < 1024; item += 256) {
        int c = item & 127, u = item >> 7;
        const float* Xc = Xs + c * 17;
        float m[8];
#pragma unroll
        for (int e = 0; e < 8; e++) {
            int gt = q0 * 64 + u * 8 + e;
            if (gt < NT3) {
                unsigned uu = sIdx[gt];
                m[e] = Xc[uu & 255] * Xc[(uu >> 8) & 255] * Xc[(uu >> 16) & 255];
            } else m[e] = 0.f;
        }
        uint32_t h[4];
#pragma unroll
        for (int p = 0; p < 4; p++) {
            __half2 hp = __floats2half2_rn(m[2 * p], m[2 * p + 1]);
            h[p] = *(uint32_t*)&hp;
        }
        uint32_t doff = (uint32_t)(c * 128 + ((u ^ (c & 7)) << 4));
        *(uint4*)(smc + OFF_A0 + doff) = make_uint4(h[0], h[1], h[2], h[3]);
    }
    CP_WAIT0();
    __syncthreads();                       // A(q0) + B(q0) visible to all

    float acc[16][4];
#pragma unroll
    for (int nt = 0; nt < 16; nt++)
#pragma unroll
        for (int k = 0; k < 4; k++) acc[nt][k] = 0.f;

    const int rw = wid & 3, cw = wid >> 2;
    const int R0 = rw * 32, C0 = cw * 64;
    const int mat = lane >> 3, lr = lane & 7;
    const int g = lane >> 2;

    for (int i = 0, q = q0; q < q1; ++i, ++q) {
        const uint32_t bufA = (i & 1) ? OFF_A1 : OFF_A0;
        const uint32_t bufAn = (i & 1) ? OFF_A0 : OFF_A1;
        const uint32_t bufB = (i & 1) ? OFF_B1 : OFF_B0;
        const uint32_t bufBn = (i & 1) ? OFF_B0 : OFF_B1;

        if (q + 1 < q1) {
            // stream B(q+1) into alternate buffer (last read of that buffer
            // finished before the previous iteration's closing barrier)
            const char* srcH = (const char*)g_B3hi + (q + 1) * 16384;
            const char* srcL = (const char*)g_B3lo + (q + 1) * 16384;
            for (int ii = tid; ii < 1024; ii += 256) {
                int row = ii >> 3, u = ii & 7;
                uint32_t doff = (uint32_t)(row * 128 + ((u ^ (row & 7)) << 4));
                int soff = (row * 64 + u * 8) * 2;
                cp16(sb + bufBn + doff, srcH + soff);
                cp16(sb + bufBn + 16384 + doff, srcL + soff);
            }
            CP_COMMIT();
            // build A(q+1) into alternate buffer -- no barrier between this
            // and MMA(q): independent buffers, warps overlap pipes freely
            for (int item = tid; item < 1024; item += 256) {
                int c = item & 127, u = item >> 7;
                const float* Xc = Xs + c * 17;
                float m[8];
#pragma unroll
                for (int e = 0; e < 8; e++) {
                    int gt = (q + 1) * 64 + u * 8 + e;
                    if (gt < NT3) {
                        unsigned uu = sIdx[gt];
                        m[e] = Xc[uu & 255] * Xc[(uu >> 8) & 255] * Xc[(uu >> 16) & 255];
                    } else m[e] = 0.f;
                }
                uint32_t h[4];
#pragma unroll
                for (int p = 0; p < 4; p++) {
                    __half2 hp = __floats2half2_rn(m[2 * p], m[2 * p + 1]);
                    h[p] = *(uint32_t*)&hp;
                }
                uint32_t doff = (uint32_t)(c * 128 + ((u ^ (c & 7)) << 4));
                *(uint4*)(smc + bufAn + doff) = make_uint4(h[0], h[1], h[2], h[3]);
            }
        }

        // MMA(q): 4 k-steps; warp tile 32 rows x 64 cols; B hi + lo terms
#pragma unroll
        for (int s = 0; s < 4; s++) {
            const int u0 = s * 2;
            uint32_t ah0[4], ah1[4];
            {
                int arow = R0 + lr + (mat & 1) * 8;
                int au = u0 + (mat >> 1);
                ldsm4(ah0, sb + bufA + (uint32_t)(arow * 128 + ((au ^ (arow & 7)) << 4)));
                int arow1 = arow + 16;
                ldsm4(ah1, sb + bufA + (uint32_t)(arow1 * 128 + ((au ^ (arow1 & 7)) << 4)));
            }
#pragma unroll
            for (int p = 0; p < 4; p++) {
                int brow = C0 + p * 16 + (mat >> 1) * 8 + lr;
                int bu = u0 + (mat & 1);
                uint32_t boff = (uint32_t)(brow * 128 + ((bu ^ (brow & 7)) << 4));
                uint32_t bh[4], bl[4];
                ldsm4(bh, sb + bufB + boff);
                ldsm4(bl, sb + bufB + 16384 + boff);
                mma16816h(acc[p * 2],         ah0, bh[0], bh[1]);
                mma16816h(acc[p * 2],         ah0, bl[0], bl[1]);
                mma16816h(acc[p * 2 + 1],     ah0, bh[2], bh[3]);
                mma16816h(acc[p * 2 + 1],     ah0, bl[2], bl[3]);
                mma16816h(acc[8 + p * 2],     ah1, bh[0], bh[1]);
                mma16816h(acc[8 + p * 2],     ah1, bl[0], bl[1]);
                mma16816h(acc[8 + p * 2 + 1], ah1, bh[2], bh[3]);
                mma16816h(acc[8 + p * 2 + 1], ah1, bl[2], bl[3]);
            }
        }
        CP_WAIT0();        // B(q+1) landed (own thread's copies)
        __syncthreads();   // A(q+1)/B(q+1) ready; MMA(q) done reading buffers
    }

    // ===== epilogue: weight by wy, reduce cols (shfl) + col-groups (smem) ====
    float* red = (float*)(smc + OFF_A0);   // alias A0 (free after loop + sync)
    const float* wyb = g_wy + b * NWY * NC;
    float ct[4][4];
#pragma unroll
    for (int a = 0; a < 4; a++)
#pragma unroll
        for (int t = 0; t < 4; t++) ct[a][t] = 0.f;
#pragma unroll
    for (int mi = 0; mi < 2; mi++) {
        int ra = R0 + mi * 16 + g;
        int rb = ra + 8;
#pragma unroll
        for (int ni = 0; ni < 8; ni++) {
#pragma unroll
            for (int hh = 0; hh < 2; hh++) {
                int j = C0 + ni * 8 + 2 * (lane & 3) + hh;
                if (j < 122) {
                    int tgt, wyc;
                    if (j < 23) { tgt = 0; wyc = j; }
                    else { int wq = (j - 23) / 33; tgt = 1 + wq; wyc = 23 + (j - 23 - wq * 33); }
                    ct[mi * 2 + 0][tgt] += acc[mi * 8 + ni][hh]     * wyb[wyc * NC + ra];
                    ct[mi * 2 + 1][tgt] += acc[mi * 8 + ni][2 + hh] * wyb[wyc * NC + rb];
                }
            }
        }
    }
#pragma unroll
    for (int a = 0; a < 4; a++)
#pragma unroll
        for (int t = 0; t < 4; t++) {
            ct[a][t] += __shfl_xor_sync(0xffffffffu, ct[a][t], 1);
            ct[a][t] += __shfl_xor_sync(0xffffffffu, ct[a][t], 2);
        }
    if ((lane & 3) == 0) {
#pragma unroll
        for (int mi = 0; mi < 2; mi++) {
            int ra = R0 + mi * 16 + g;
#pragma unroll
            for (int t = 0; t < 4; t++) {
                red[(cw * 128 + ra) * 4 + t]     = ct[mi * 2 + 0][t];
                red[(cw * 128 + ra + 8) * 4 + t] = ct[mi * 2 + 1][t];
            }
        }
    }
    __syncthreads();
    for (int i = tid; i < 512; i += 256) {
        int row = i >> 2, tgt = i & 3;
        float v = red[row * 4 + tgt] + red[(128 + row) * 4 + tgt];
        float* ob = out + b * 512;
        if (tgt == 0) atomicAdd(&ob[row], v);
        else atomicAdd(&ob[128 + 3 * row + (tgt - 1)], v);
    }
}

extern "C" void kernel_launch(void* const* d_in, const int* in_sizes, int n_in,
                              void* d_out, int out_size) {
    const float* x      = (const float*)d_in[0];
    const float* y      = (const float*)d_in[1];
    const float* U1_0e  = (const float*)d_in[2];
    const float* U2_0e  = (const float*)d_in[3];
    const float* U3_0e  = (const float*)d_in[4];
    const float* U1_1o  = (const float*)d_in[5];
    const float* U2_1o  = (const float*)d_in[6];
    const float* U3_1o  = (const float*)d_in[7];
    const float* w1_0e  = (const float*)d_in[8];
    const float* w2_0e  = (const float*)d_in[9];
    const float* w3_0e  = (const float*)d_in[10];
    const float* w1_1o  = (const float*)d_in[11];
    const float* w2_1o  = (const float*)d_in[12];
    const float* w3_1o  = (const float*)d_in[13];
    float* out = (float*)d_out;

    cudaFuncSetAttribute(k_main, cudaFuncAttributeMaxDynamicSharedMemorySize, SMEM_TOTAL);

    k_setup<<<130, 256>>>(U1_0e, U2_0e, U3_0e, U1_1o, U2_1o, U3_1o);
    k_wy<<<NB, 256>>>(y, x, w3_0e, w3_1o, w2_0e, w2_1o, w1_0e, w1_1o, out);
    k_main<<<2 * NB, 256, SMEM_TOTAL>>>(x, out);
}

// round 12
// speedup vs baseline: 1.0809x; 1.0809x over previous
#include <cuda_runtime.h>
#include <cuda_fp16.h>
#include <cstdint>

#define L    16
#define NB   128
#define NC   128
#define NE   10
#define NT3  816
#define NT3P 832      // padded to 13*64
#define NT2  136
#define COLS2 24
#define NWY  68
#define NCHUNK 13     // K chunks of 64

typedef unsigned long long ull;

// ---------------- device globals ----------------
__device__ unsigned g_idx3[NT3];
__device__ unsigned g_idx2[NT2];
__device__ float    g_Us2[NT2 * COLS2];
__device__ float    g_Us1[L * 4];
__device__ float    g_wy[NB * NWY * NC];
// split-fp16 coefficient chunk images, row-major: [chunk][j=128][t_in=64]
__device__ __align__(16) __half g_B3hi[NCHUNK * 8192];
__device__ __align__(16) __half g_B3lo[NCHUNK * 8192];

// ---------------- helpers ----------------
__device__ __forceinline__ uint32_t smem_u32(const void* p) {
    uint32_t a;
    asm("{ .reg .u64 t; cvta.to.shared.u64 t, %1; cvt.u32.u64 %0, t; }" : "=r"(a) : "l"(p));
    return a;
}
__device__ __forceinline__ ull pack2(float v) {
    ull r; asm("mov.b64 %0, {%1, %1};" : "=l"(r) : "f"(v)); return r;
}
__device__ __forceinline__ void unpack2(ull v, float& lo, float& hi) {
    asm("mov.b64 {%0, %1}, %2;" : "=f"(lo), "=f"(hi) : "l"(v));
}
__device__ __forceinline__ void fma2(ull& d, ull a, ull b) {
    asm("fma.rn.f32x2 %0, %1, %2, %0;" : "+l"(d) : "l"(a), "l"(b));
}
__device__ __forceinline__ void ldsm4(uint32_t* r, uint32_t addr) {
    asm volatile("ldmatrix.sync.aligned.m8n8.x4.shared.b16 {%0,%1,%2,%3}, [%4];"
                 : "=r"(r[0]), "=r"(r[1]), "=r"(r[2]), "=r"(r[3]) : "r"(addr));
}
__device__ __forceinline__ void mma16816h(float* d, const uint32_t* a,
                                          uint32_t b0, uint32_t b1) {
    asm volatile("mma.sync.aligned.m16n8k16.row.col.f32.f16.f16.f32 "
                 "{%0,%1,%2,%3}, {%4,%5,%6,%7}, {%8,%9}, {%0,%1,%2,%3};"
                 : "+f"(d[0]), "+f"(d[1]), "+f"(d[2]), "+f"(d[3])
                 : "r"(a[0]), "r"(a[1]), "r"(a[2]), "r"(a[3]), "r"(b0), "r"(b1));
}
__device__ __forceinline__ void cp16(uint32_t daddr, const void* gsrc) {
    asm volatile("cp.async.cg.shared.global [%0], [%1], 16;"
                 :: "r"(daddr), "l"(gsrc) : "memory");
}
#define CP_COMMIT() asm volatile("cp.async.commit_group;" ::: "memory")
#define CP_WAIT0()  asm volatile("cp.async.wait_group 0;" ::: "memory")

// ---------------- K0: symmetrize + fp16-split (R10 version, 7.9us) --------
// blocks [0,832): triple t (>=816 -> zeros); [832,968): pair; 968: order-1.
__global__ void k_setup(const float* __restrict__ U1_0e, const float* __restrict__ U2_0e,
                        const float* __restrict__ U3_0e, const float* __restrict__ U1_1o,
                        const float* __restrict__ U2_1o, const float* __restrict__ U3_1o) {
    int blk = blockIdx.x;
    int j = threadIdx.x;
    if (blk < NT3P) {
        int t = blk;
        float val = 0.f;
        if (t < NT3) {
            int rem = t, A = 0, B = 0, D = 0;
            {
                int i = 0;
                for (;;) { int m = L - i; int cnt = m * (m + 1) / 2;
                           if (rem < cnt) break; rem -= cnt; i++; }
                A = i;
                int q = A;
                for (;;) { int cnt = L - q;
                           if (rem < cnt) break; rem -= cnt; q++; }
                B = q; D = B + rem;
            }
            if (j == 0) g_idx3[t] = (unsigned)A | ((unsigned)B << 8) | ((unsigned)D << 16);
            int P[6][3] = {{A,B,D},{A,D,B},{B,A,D},{B,D,A},{D,A,B},{D,B,A}};
            if (j < 122) {
                for (int i = 0; i < 6; i++) {
                    bool dup = false;
                    for (int q = 0; q < i; q++)
                        if (P[q][0] == P[i][0] && P[q][1] == P[i][1] && P[q][2] == P[i][2]) dup = true;
                    if (dup) continue;
                    int p0 = P[i][0], p1 = P[i][1], p2 = P[i][2];
                    if (j < 23) {
                        val += U3_0e[((p0 * L + p1) * L + p2) * 23 + j];
                    } else {
                        int w = (j - 23) / 33, k = (j - 23) % 33;
                        val += U3_1o[(((w * L + p0) * L + p1) * L + p2) * 33 + k];
                    }
                }
            }
        }
        __half hv = __float2half_rn(val);
        __half lv = __float2half_rn(val - __half2float(hv));
        int chunk = t >> 6, t_in = t & 63;
        g_B3hi[chunk * 8192 + j * 64 + t_in] = hv;
        g_B3lo[chunk * 8192 + j * 64 + t_in] = lv;
    } else if (blk < NT3P + NT2) {
        int t = blk - NT3P;
        int rem = t, A = 0, B = 0;
        {
            int i = 0;
            for (;;) { int cnt = L - i;
                       if (rem < cnt) break; rem -= cnt; i++; }
            A = i; B = A + rem;
        }
        if (j == 0) g_idx2[t] = (unsigned)A | ((unsigned)B << 8);
        if (j >= COLS2) return;
        float val = 0.f;
        if (j < 22) {
            if (j < 4) {
                val = U2_0e[(A * L + B) * 4 + j];
                if (A != B) val += U2_0e[(B * L + A) * 4 + j];
            } else {
                int w = (j - 4) / 6, k = (j - 4) % 6;
                val = U2_1o[((w * L + A) * L + B) * 6 + k];
                if (A != B) val += U2_1o[((w * L + B) * L + A) * 6 + k];
            }
        }
        g_Us2[t * COLS2 + j] = val;
    } else {
        if (j >= L * 4) return;
        int a = j >> 2, col = j & 3;
        g_Us1[a * 4 + col] = (col == 0) ? U1_0e[a] : U1_1o[(col - 1) * L + a];
    }
}

// ---------------- K1: wy + order-1/2 + output base (unchanged, passing) ----
__global__ void __launch_bounds__(256) k_wy(
        const float* __restrict__ y, const float* __restrict__ x,
        const float* __restrict__ w3_0e, const float* __restrict__ w3_1o,
        const float* __restrict__ w2_0e, const float* __restrict__ w2_1o,
        const float* __restrict__ w1_0e, const float* __restrict__ w1_1o,
        float* __restrict__ out) {
    __shared__ __align__(16) float ys[NE];
    __shared__ __align__(16) float Xs[NC * 17];
    __shared__ __align__(16) float wys[12 * NC];
    __shared__ __align__(16) float Us2s[NT2 * COLS2];
    __shared__ __align__(16) float Us1s[L * 4];
    __shared__ __align__(16) float red2[NC * 4 * 2];
    const int tid = threadIdx.x;
    const int b = blockIdx.x;

    if (tid < NE) ys[tid] = y[b * NE + tid];
    if (tid < L * 4) Us1s[tid] = g_Us1[tid];
    {
        int c = tid >> 1, off = (tid & 1) * 8;
        const float4* xp = (const float4*)(x + (b * NC + c) * L + off);
        float4 v0 = xp[0], v1 = xp[1];
        float* dst = Xs + c * 17 + off;
        dst[0] = v0.x; dst[1] = v0.y; dst[2] = v0.z; dst[3] = v0.w;
        dst[4] = v1.x; dst[5] = v1.y; dst[6] = v1.z; dst[7] = v1.w;
    }
    for (int i = tid; i < NT2 * (COLS2 / 4); i += 256)
        ((float4*)Us2s)[i] = ((const float4*)g_Us2)[i];
    __syncthreads();

    for (int idx = tid; idx < NWY * NC; idx += 256) {
        int jw = idx >> 7, c = idx & 127;
        const float* wsrc; int K, k;
        if (jw < 23)       { wsrc = w3_0e; K = 23; k = jw; }
        else if (jw < 56)  { wsrc = w3_1o; K = 33; k = jw - 23; }
        else if (jw < 60)  { wsrc = w2_0e; K = 4;  k = jw - 56; }
        else if (jw < 66)  { wsrc = w2_1o; K = 6;  k = jw - 60; }
        else if (jw == 66) { wsrc = w1_0e; K = 1;  k = 0; }
        else               { wsrc = w1_1o; K = 1;  k = 0; }
        float acc = 0.f;
#pragma unroll
        for (int e = 0; e < NE; e++)
            acc = fmaf(wsrc[(e * K + k) * NC + c], ys[e], acc);
        g_wy[(b * NWY + jw) * NC + c] = acc;
        if (jw >= 56) wys[(jw - 56) * NC + c] = acc;
    }
    __syncthreads();

    const int c = tid & 127;
    const int half = tid >> 7;
    const float* Xc = Xs + c * 17;
    ull P2[11];
#pragma unroll
    for (int k = 0; k < 11; k++) P2[k] = 0ull;
    for (int t = half * 68; t < half * 68 + 68; t++) {
        unsigned u = g_idx2[t];
        ull m2 = pack2(Xc[u & 255] * Xc[(u >> 8) & 255]);
        const ull* row = (const ull*)(Us2s + t * COLS2);
#pragma unroll
        for (int k = 0; k < 11; k++) fma2(P2[k], m2, row[k]);
    }
    float contrib[4] = {0.f, 0.f, 0.f, 0.f};
#pragma unroll
    for (int k = 0; k < 11; k++) {
        float lo, hi;
        unpack2(P2[k], lo, hi);
#pragma unroll
        for (int hh = 0; hh < 2; hh++) {
            int j = 2 * k + hh;
            float v = (hh == 0) ? lo : hi;
            int tgt, row;
            if (j < 4) { tgt = 0; row = j; }
            else { int wq = (j - 4) / 6; tgt = 1 + wq; row = 4 + (j - 4 - wq * 6); }
            contrib[tgt] += v * wys[row * NC + c];
        }
    }
    if (half == 0) {
        float P0 = 0.f, P1 = 0.f, Pq = 0.f, P3 = 0.f;
#pragma unroll
        for (int a = 0; a < L; a++) {
            float xa = Xc[a];
            P0 = fmaf(Us1s[a * 4 + 0], xa, P0);
            P1 = fmaf(Us1s[a * 4 + 1], xa, P1);
            Pq = fmaf(Us1s[a * 4 + 2], xa, Pq);
            P3 = fmaf(Us1s[a * 4 + 3], xa, P3);
        }
        contrib[0] = fmaf(P0, wys[10 * NC + c], contrib[0]);
        contrib[1] = fmaf(P1, wys[11 * NC + c], contrib[1]);
        contrib[2] = fmaf(Pq, wys[11 * NC + c], contrib[2]);
        contrib[3] = fmaf(P3, wys[11 * NC + c], contrib[3]);
    }
#pragma unroll
    for (int tgt = 0; tgt < 4; tgt++)
        red2[(c * 4 + tgt) * 2 + half] = contrib[tgt];
    __syncthreads();
    for (int i = tid; i < 512; i += 256) {
        int cc = i >> 2, tgt = i & 3;
        float v = red2[i * 2] + red2[i * 2 + 1];
        if (tgt == 0) out[b * 512 + cc] = v;
        else out[b * 512 + 128 + 3 * cc + (tgt - 1)] = v;
    }
}

// ---------------- K2: order-3 HMMA fp16, fused build+MMA pipeline ----------
// grid = 256: (atom b, K-half kh). 8 warps = 4 row-groups x 2 col-groups.
// smem: A0 16K | A1 16K | B0 32K | B1 32K | Xs 8.5K | idx 3.3K  = ~110K
#define OFF_A0   0
#define OFF_A1   16384
#define OFF_B0   32768
#define OFF_B1   65536
#define OFF_XS   98304
#define OFF_IDX  107008
#define SMEM_TOTAL 110336

__global__ void __launch_bounds__(256, 2) k_main(const float* __restrict__ x,
                                                 float* __restrict__ out) {
    extern __shared__ __align__(1024) char smc[];
    const uint32_t sb = smem_u32(smc);
    const int tid = threadIdx.x;
    const int wid = tid >> 5;
    const int lane = tid & 31;
    const int b = blockIdx.x >> 1;
    const int kh = blockIdx.x & 1;
    const int q0 = kh ? 7 : 0;
    const int q1 = kh ? NCHUNK : 7;

    float* Xs = (float*)(smc + OFF_XS);
    unsigned* sIdx = (unsigned*)(smc + OFF_IDX);

    // prologue: stream B(q0), stage X + idx
    {
        const char* srcH = (const char*)g_B3hi + q0 * 16384;
        const char* srcL = (const char*)g_B3lo + q0 * 16384;
        for (int i = tid; i < 1024; i += 256) {
            int row = i >> 3, u = i & 7;
            uint32_t doff = (uint32_t)(row * 128 + ((u ^ (row & 7)) << 4));
            int soff = (row * 64 + u * 8) * 2;
            cp16(sb + OFF_B0 + doff, srcH + soff);
            cp16(sb + OFF_B0 + 16384 + doff, srcL + soff);
        }
        CP_COMMIT();
    }
    {
        int c = tid >> 1, off = (tid & 1) * 8;
        const float4* xp = (const float4*)(x + (b * NC + c) * L + off);
        float4 v0 = xp[0], v1 = xp[1];
        float* dst = Xs + c * 17 + off;
        dst[0] = v0.x; dst[1] = v0.y; dst[2] = v0.z; dst[3] = v0.w;
        dst[4] = v1.x; dst[5] = v1.y; dst[6] = v1.z; dst[7] = v1.w;
    }
    for (int i = tid; i < NT3; i += 256) sIdx[i] = g_idx3[i];
    __syncthreads();                       // Xs/idx ready for build

    // build A(q0) -> A0
    for (int item = tid; item < 1024; item += 256) {
        int c = item & 127, u = item >> 7;
        const float* Xc = Xs + c * 17;
        float m[8];
#pragma unroll
        for (int e = 0; e < 8; e++) {
            int gt = q0 * 64 + u * 8 + e;
            if (gt < NT3) {
                unsigned uu = sIdx[gt];
                m[e] = Xc[uu & 255] * Xc[(uu >> 8) & 255] * Xc[(uu >> 16) & 255];
            } else m[e] = 0.f;
        }
        uint32_t h[4];
#pragma unroll
        for (int p = 0; p < 4; p++) {
            __half2 hp = __floats2half2_rn(m[2 * p], m[2 * p + 1]);
            h[p] = *(uint32_t*)&hp;
        }
        uint32_t doff = (uint32_t)(c * 128 + ((u ^ (c & 7)) << 4));
        *(uint4*)(smc + OFF_A0 + doff) = make_uint4(h[0], h[1], h[2], h[3]);
    }
    CP_WAIT0();
    __syncthreads();                       // A(q0) + B(q0) visible to all

    float acc[16][4];
#pragma unroll
    for (int nt = 0; nt < 16; nt++)
#pragma unroll
        for (int k = 0; k < 4; k++) acc[nt][k] = 0.f;

    const int rw = wid & 3, cw = wid >> 2;
    const int R0 = rw * 32, C0 = cw * 64;
    const int mat = lane >> 3, lr = lane & 7;
    const int g = lane >> 2;

    for (int i = 0, q = q0; q < q1; ++i, ++q) {
        const uint32_t bufA = (i & 1) ? OFF_A1 : OFF_A0;
        const uint32_t bufAn = (i & 1) ? OFF_A0 : OFF_A1;
        const uint32_t bufB = (i & 1) ? OFF_B1 : OFF_B0;
        const uint32_t bufBn = (i & 1) ? OFF_B0 : OFF_B1;

        if (q + 1 < q1) {
            // stream B(q+1) into alternate buffer
            const char* srcH = (const char*)g_B3hi + (q + 1) * 16384;
            const char* srcL = (const char*)g_B3lo + (q + 1) * 16384;
            for (int ii = tid; ii < 1024; ii += 256) {
                int row = ii >> 3, u = ii & 7;
                uint32_t doff = (uint32_t)(row * 128 + ((u ^ (row & 7)) << 4));
                int soff = (row * 64 + u * 8) * 2;
                cp16(sb + bufBn + doff, srcH + soff);
                cp16(sb + bufBn + 16384 + doff, srcL + soff);
            }
            CP_COMMIT();
            // build A(q+1) into alternate buffer -- no barrier between this
            // and MMA(q): independent buffers, warps overlap pipes freely
            for (int item = tid; item < 1024; item += 256) {
                int c = item & 127, u = item >> 7;
                const float* Xc = Xs + c * 17;
                float m[8];
#pragma unroll
                for (int e = 0; e < 8; e++) {
                    int gt = (q + 1) * 64 + u * 8 + e;
                    if (gt < NT3) {
                        unsigned uu = sIdx[gt];
                        m[e] = Xc[uu & 255] * Xc[(uu >> 8) & 255] * Xc[(uu >> 16) & 255];
                    } else m[e] = 0.f;
                }
                uint32_t h[4];
#pragma unroll
                for (int p = 0; p < 4; p++) {
                    __half2 hp = __floats2half2_rn(m[2 * p], m[2 * p + 1]);
                    h[p] = *(uint32_t*)&hp;
                }
                uint32_t doff = (uint32_t)(c * 128 + ((u ^ (c & 7)) << 4));
                *(uint4*)(smc + bufAn + doff) = make_uint4(h[0], h[1], h[2], h[3]);
            }
        }

        // MMA(q): 4 k-steps; warp tile 32 rows x 64 cols; B hi + lo terms
#pragma unroll
        for (int s = 0; s < 4; s++) {
            const int u0 = s * 2;
            uint32_t ah0[4], ah1[4];
            {
                int arow = R0 + lr + (mat & 1) * 8;
                int au = u0 + (mat >> 1);
                ldsm4(ah0, sb + bufA + (uint32_t)(arow * 128 + ((au ^ (arow & 7)) << 4)));
                int arow1 = arow + 16;
                ldsm4(ah1, sb + bufA + (uint32_t)(arow1 * 128 + ((au ^ (arow1 & 7)) << 4)));
            }
#pragma unroll
            for (int p = 0; p < 4; p++) {
                int brow = C0 + p * 16 + (mat >> 1) * 8 + lr;
                int bu = u0 + (mat & 1);
                uint32_t boff = (uint32_t)(brow * 128 + ((bu ^ (brow & 7)) << 4));
                uint32_t bh[4], bl[4];
                ldsm4(bh, sb + bufB + boff);
                ldsm4(bl, sb + bufB + 16384 + boff);
                mma16816h(acc[p * 2],         ah0, bh[0], bh[1]);
                mma16816h(acc[p * 2],         ah0, bl[0], bl[1]);
                mma16816h(acc[p * 2 + 1],     ah0, bh[2], bh[3]);
                mma16816h(acc[p * 2 + 1],     ah0, bl[2], bl[3]);
                mma16816h(acc[8 + p * 2],     ah1, bh[0], bh[1]);
                mma16816h(acc[8 + p * 2],     ah1, bl[0], bl[1]);
                mma16816h(acc[8 + p * 2 + 1], ah1, bh[2], bh[3]);
                mma16816h(acc[8 + p * 2 + 1], ah1, bl[2], bl[3]);
            }
        }
        CP_WAIT0();        // B(q+1) landed (own thread's copies)
        __syncthreads();   // A(q+1)/B(q+1) ready; MMA(q) done reading buffers
    }

    // ===== epilogue: weight by wy, reduce cols (shfl) + col-groups (smem) ====
    float* red = (float*)(smc + OFF_A0);   // alias A0 (free after loop + sync)
    const float* wyb = g_wy + b * NWY * NC;
    float ct[4][4];
#pragma unroll
    for (int a = 0; a < 4; a++)
#pragma unroll
        for (int t = 0; t < 4; t++) ct[a][t] = 0.f;
#pragma unroll
    for (int mi = 0; mi < 2; mi++) {
        int ra = R0 + mi * 16 + g;
        int rb = ra + 8;
#pragma unroll
        for (int ni = 0; ni < 8; ni++) {
#pragma unroll
            for (int hh = 0; hh < 2; hh++) {
                int j = C0 + ni * 8 + 2 * (lane & 3) + hh;
                if (j < 122) {
                    int tgt, wyc;
                    if (j < 23) { tgt = 0; wyc = j; }
                    else { int wq = (j - 23) / 33; tgt = 1 + wq; wyc = 23 + (j - 23 - wq * 33); }
                    ct[mi * 2 + 0][tgt] += acc[mi * 8 + ni][hh]     * wyb[wyc * NC + ra];
                    ct[mi * 2 + 1][tgt] += acc[mi * 8 + ni][2 + hh] * wyb[wyc * NC + rb];
                }
            }
        }
    }
#pragma unroll
    for (int a = 0; a < 4; a++)
#pragma unroll
        for (int t = 0; t < 4; t++) {
            ct[a][t] += __shfl_xor_sync(0xffffffffu, ct[a][t], 1);
            ct[a][t] += __shfl_xor_sync(0xffffffffu, ct[a][t], 2);
        }
    if ((lane & 3) == 0) {
#pragma unroll
        for (int mi = 0; mi < 2; mi++) {
            int ra = R0 + mi * 16 + g;
#pragma unroll
            for (int t = 0; t < 4; t++) {
                red[(cw * 128 + ra) * 4 + t]     = ct[mi * 2 + 0][t];
                red[(cw * 128 + ra + 8) * 4 + t] = ct[mi * 2 + 1][t];
            }
        }
    }
    __syncthreads();
    for (int i = tid; i < 512; i += 256) {
        int row = i >> 2, tgt = i & 3;
        float v = red[row * 4 + tgt] + red[(128 + row) * 4 + tgt];
        float* ob = out + b * 512;
        if (tgt == 0) atomicAdd(&ob[row], v);
        else atomicAdd(&ob[128 + 3 * row + (tgt - 1)], v);
    }
}

extern "C" void kernel_launch(void* const* d_in, const int* in_sizes, int n_in,
                              void* d_out, int out_size) {
    const float* x      = (const float*)d_in[0];
    const float* y      = (const float*)d_in[1];
    const float* U1_0e  = (const float*)d_in[2];
    const float* U2_0e  = (const float*)d_in[3];
    const float* U3_0e  = (const float*)d_in[4];
    const float* U1_1o  = (const float*)d_in[5];
    const float* U2_1o  = (const float*)d_in[6];
    const float* U3_1o  = (const float*)d_in[7];
    const float* w1_0e  = (const float*)d_in[8];
    const float* w2_0e  = (const float*)d_in[9];
    const float* w3_0e  = (const float*)d_in[10];
    const float* w1_1o  = (const float*)d_in[11];
    const float* w2_1o  = (const float*)d_in[12];
    const float* w3_1o  = (const float*)d_in[13];
    float* out = (float*)d_out;

    cudaFuncSetAttribute(k_main, cudaFuncAttributeMaxDynamicSharedMemorySize, SMEM_TOTAL);

    k_setup<<<NT3P + NT2 + 1, 128>>>(U1_0e, U2_0e, U3_0e, U1_1o, U2_1o, U3_1o);
    k_wy<<<NB, 256>>>(y, x, w3_0e, w3_1o, w2_0e, w2_1o, w1_0e, w1_1o, out);
    k_main<<<2 * NB, 256, SMEM_TOTAL>>>(x, out);
}

// round 13
// speedup vs baseline: 1.2042x; 1.1141x over previous
#include <cuda_runtime.h>
#include <cuda_fp16.h>
#include <cstdint>

#define L    16
#define NB   128
#define NC   128
#define NE   10
#define NT3  816
#define NT3P 832      // padded to 13*64
#define NT2  136
#define COLS2 24
#define NWY  68
#define NCHUNK 13     // K chunks of 64

typedef unsigned long long ull;

// ---------------- device globals ----------------
__device__ unsigned g_idx3[NT3];
__device__ unsigned g_idx2[NT2];
__device__ float    g_Us2[NT2 * COLS2];
__device__ float    g_Us1[L * 4];
__device__ float    g_wy[NB * NWY * NC];
// fp16 coefficient chunk images, row-major: [chunk][j=128][t_in=64]
__device__ __align__(16) __half g_B3hi[NCHUNK * 8192];

// ---------------- helpers ----------------
__device__ __forceinline__ uint32_t smem_u32(const void* p) {
    uint32_t a;
    asm("{ .reg .u64 t; cvta.to.shared.u64 t, %1; cvt.u32.u64 %0, t; }" : "=r"(a) : "l"(p));
    return a;
}
__device__ __forceinline__ ull pack2(float v) {
    ull r; asm("mov.b64 %0, {%1, %1};" : "=l"(r) : "f"(v)); return r;
}
__device__ __forceinline__ void unpack2(ull v, float& lo, float& hi) {
    asm("mov.b64 {%0, %1}, %2;" : "=f"(lo), "=f"(hi) : "l"(v));
}
__device__ __forceinline__ void fma2(ull& d, ull a, ull b) {
    asm("fma.rn.f32x2 %0, %1, %2, %0;" : "+l"(d) : "l"(a), "l"(b));
}
__device__ __forceinline__ void ldsm4(uint32_t* r, uint32_t addr) {
    asm volatile("ldmatrix.sync.aligned.m8n8.x4.shared.b16 {%0,%1,%2,%3}, [%4];"
                 : "=r"(r[0]), "=r"(r[1]), "=r"(r[2]), "=r"(r[3]) : "r"(addr));
}
__device__ __forceinline__ void mma16816h(float* d, const uint32_t* a,
                                          uint32_t b0, uint32_t b1) {
    asm volatile("mma.sync.aligned.m16n8k16.row.col.f32.f16.f16.f32 "
                 "{%0,%1,%2,%3}, {%4,%5,%6,%7}, {%8,%9}, {%0,%1,%2,%3};"
                 : "+f"(d[0]), "+f"(d[1]), "+f"(d[2]), "+f"(d[3])
                 : "r"(a[0]), "r"(a[1]), "r"(a[2]), "r"(a[3]), "r"(b0), "r"(b1));
}
__device__ __forceinline__ void cp16(uint32_t daddr, const void* gsrc) {
    asm volatile("cp.async.cg.shared.global [%0], [%1], 16;"
                 :: "r"(daddr), "l"(gsrc) : "memory");
}
#define CP_COMMIT() asm volatile("cp.async.commit_group;" ::: "memory")
#define CP_WAIT0()  asm volatile("cp.async.wait_group 0;" ::: "memory")

// ---------------- K0: symmetrize + fp16 quantize ----------------
// blocks [0,832): triple t (>=816 -> zeros); [832,968): pair; 968: order-1.
__global__ void k_setup(const float* __restrict__ U1_0e, const float* __restrict__ U2_0e,
                        const float* __restrict__ U3_0e, const float* __restrict__ U1_1o,
                        const float* __restrict__ U2_1o, const float* __restrict__ U3_1o) {
    int blk = blockIdx.x;
    int j = threadIdx.x;
    if (blk < NT3P) {
        int t = blk;
        float val = 0.f;
        if (t < NT3) {
            int rem = t, A = 0, B = 0, D = 0;
            {
                int i = 0;
                for (;;) { int m = L - i; int cnt = m * (m + 1) / 2;
                           if (rem < cnt) break; rem -= cnt; i++; }
                A = i;
                int q = A;
                for (;;) { int cnt = L - q;
                           if (rem < cnt) break; rem -= cnt; q++; }
                B = q; D = B + rem;
            }
            if (j == 0) g_idx3[t] = (unsigned)A | ((unsigned)B << 8) | ((unsigned)D << 16);
            int P[6][3] = {{A,B,D},{A,D,B},{B,A,D},{B,D,A},{D,A,B},{D,B,A}};
            if (j < 122) {
                for (int i = 0; i < 6; i++) {
                    bool dup = false;
                    for (int q = 0; q < i; q++)
                        if (P[q][0] == P[i][0] && P[q][1] == P[i][1] && P[q][2] == P[i][2]) dup = true;
                    if (dup) continue;
                    int p0 = P[i][0], p1 = P[i][1], p2 = P[i][2];
                    if (j < 23) {
                        val += U3_0e[((p0 * L + p1) * L + p2) * 23 + j];
                    } else {
                        int w = (j - 23) / 33, k = (j - 23) % 33;
                        val += U3_1o[(((w * L + p0) * L + p1) * L + p2) * 33 + k];
                    }
                }
            }
        }
        int chunk = t >> 6, t_in = t & 63;
        g_B3hi[chunk * 8192 + j * 64 + t_in] = __float2half_rn(val);
    } else if (blk < NT3P + NT2) {
        int t = blk - NT3P;
        int rem = t, A = 0, B = 0;
        {
            int i = 0;
            for (;;) { int cnt = L - i;
                       if (rem < cnt) break; rem -= cnt; i++; }
            A = i; B = A + rem;
        }
        if (j == 0) g_idx2[t] = (unsigned)A | ((unsigned)B << 8);
        if (j >= COLS2) return;
        float val = 0.f;
        if (j < 22) {
            if (j < 4) {
                val = U2_0e[(A * L + B) * 4 + j];
                if (A != B) val += U2_0e[(B * L + A) * 4 + j];
            } else {
                int w = (j - 4) / 6, k = (j - 4) % 6;
                val = U2_1o[((w * L + A) * L + B) * 6 + k];
                if (A != B) val += U2_1o[((w * L + B) * L + A) * 6 + k];
            }
        }
        g_Us2[t * COLS2 + j] = val;
    } else {
        if (j >= L * 4) return;
        int a = j >> 2, col = j & 3;
        g_Us1[a * 4 + col] = (col == 0) ? U1_0e[a] : U1_1o[(col - 1) * L + a];
    }
}

// ---------------- K1: wy + order-1/2 + output base (unchanged, passing) ----
__global__ void __launch_bounds__(256) k_wy(
        const float* __restrict__ y, const float* __restrict__ x,
        const float* __restrict__ w3_0e, const float* __restrict__ w3_1o,
        const float* __restrict__ w2_0e, const float* __restrict__ w2_1o,
        const float* __restrict__ w1_0e, const float* __restrict__ w1_1o,
        float* __restrict__ out) {
    __shared__ __align__(16) float ys[NE];
    __shared__ __align__(16) float Xs[NC * 17];
    __shared__ __align__(16) float wys[12 * NC];
    __shared__ __align__(16) float Us2s[NT2 * COLS2];
    __shared__ __align__(16) float Us1s[L * 4];
    __shared__ __align__(16) float red2[NC * 4 * 2];
    const int tid = threadIdx.x;
    const int b = blockIdx.x;

    if (tid < NE) ys[tid] = y[b * NE + tid];
    if (tid < L * 4) Us1s[tid] = g_Us1[tid];
    {
        int c = tid >> 1, off = (tid & 1) * 8;
        const float4* xp = (const float4*)(x + (b * NC + c) * L + off);
        float4 v0 = xp[0], v1 = xp[1];
        float* dst = Xs + c * 17 + off;
        dst[0] = v0.x; dst[1] = v0.y; dst[2] = v0.z; dst[3] = v0.w;
        dst[4] = v1.x; dst[5] = v1.y; dst[6] = v1.z; dst[7] = v1.w;
    }
    for (int i = tid; i < NT2 * (COLS2 / 4); i += 256)
        ((float4*)Us2s)[i] = ((const float4*)g_Us2)[i];
    __syncthreads();

    for (int idx = tid; idx < NWY * NC; idx += 256) {
        int jw = idx >> 7, c = idx & 127;
        const float* wsrc; int K, k;
        if (jw < 23)       { wsrc = w3_0e; K = 23; k = jw; }
        else if (jw < 56)  { wsrc = w3_1o; K = 33; k = jw - 23; }
        else if (jw < 60)  { wsrc = w2_0e; K = 4;  k = jw - 56; }
        else if (jw < 66)  { wsrc = w2_1o; K = 6;  k = jw - 60; }
        else if (jw == 66) { wsrc = w1_0e; K = 1;  k = 0; }
        else               { wsrc = w1_1o; K = 1;  k = 0; }
        float acc = 0.f;
#pragma unroll
        for (int e = 0; e < NE; e++)
            acc = fmaf(wsrc[(e * K + k) * NC + c], ys[e], acc);
        g_wy[(b * NWY + jw) * NC + c] = acc;
        if (jw >= 56) wys[(jw - 56) * NC + c] = acc;
    }
    __syncthreads();

    const int c = tid & 127;
    const int half = tid >> 7;
    const float* Xc = Xs + c * 17;
    ull P2[11];
#pragma unroll
    for (int k = 0; k < 11; k++) P2[k] = 0ull;
    for (int t = half * 68; t < half * 68 + 68; t++) {
        unsigned u = g_idx2[t];
        ull m2 = pack2(Xc[u & 255] * Xc[(u >> 8) & 255]);
        const ull* row = (const ull*)(Us2s + t * COLS2);
#pragma unroll
        for (int k = 0; k < 11; k++) fma2(P2[k], m2, row[k]);
    }
    float contrib[4] = {0.f, 0.f, 0.f, 0.f};
#pragma unroll
    for (int k = 0; k < 11; k++) {
        float lo, hi;
        unpack2(P2[k], lo, hi);
#pragma unroll
        for (int hh = 0; hh < 2; hh++) {
            int j = 2 * k + hh;
            float v = (hh == 0) ? lo : hi;
            int tgt, row;
            if (j < 4) { tgt = 0; row = j; }
            else { int wq = (j - 4) / 6; tgt = 1 + wq; row = 4 + (j - 4 - wq * 6); }
            contrib[tgt] += v * wys[row * NC + c];
        }
    }
    if (half == 0) {
        float P0 = 0.f, P1 = 0.f, Pq = 0.f, P3 = 0.f;
#pragma unroll
        for (int a = 0; a < L; a++) {
            float xa = Xc[a];
            P0 = fmaf(Us1s[a * 4 + 0], xa, P0);
            P1 = fmaf(Us1s[a * 4 + 1], xa, P1);
            Pq = fmaf(Us1s[a * 4 + 2], xa, Pq);
            P3 = fmaf(Us1s[a * 4 + 3], xa, P3);
        }
        contrib[0] = fmaf(P0, wys[10 * NC + c], contrib[0]);
        contrib[1] = fmaf(P1, wys[11 * NC + c], contrib[1]);
        contrib[2] = fmaf(Pq, wys[11 * NC + c], contrib[2]);
        contrib[3] = fmaf(P3, wys[11 * NC + c], contrib[3]);
    }
#pragma unroll
    for (int tgt = 0; tgt < 4; tgt++)
        red2[(c * 4 + tgt) * 2 + half] = contrib[tgt];
    __syncthreads();
    for (int i = tid; i < 512; i += 256) {
        int cc = i >> 2, tgt = i & 3;
        float v = red2[i * 2] + red2[i * 2 + 1];
        if (tgt == 0) out[b * 512 + cc] = v;
        else out[b * 512 + 128 + 3 * cc + (tgt - 1)] = v;
    }
}

// ---------------- K2: order-3 HMMA fp16, 1-term, fused pipeline ------------
// grid = 256: (atom b, K-half kh). 8 warps = 4 row-groups x 2 col-groups.
// smem: A0 16K | A1 16K | B0 16K | B1 16K | Xs 8.5K | idx 3.3K  = ~77.5K
#define OFF_A0   0
#define OFF_A1   16384
#define OFF_B0   32768
#define OFF_B1   49152
#define OFF_XS   65536
#define OFF_IDX  74240
#define SMEM_TOTAL 77568

__global__ void __launch_bounds__(256, 2) k_main(const float* __restrict__ x,
                                                 float* __restrict__ out) {
    extern __shared__ __align__(1024) char smc[];
    const uint32_t sb = smem_u32(smc);
    const int tid = threadIdx.x;
    const int wid = tid >> 5;
    const int lane = tid & 31;
    const int b = blockIdx.x >> 1;
    const int kh = blockIdx.x & 1;
    const int q0 = kh ? 7 : 0;
    const int q1 = kh ? NCHUNK : 7;

    float* Xs = (float*)(smc + OFF_XS);
    unsigned* sIdx = (unsigned*)(smc + OFF_IDX);

    // prologue: stream B(q0), stage X + idx
    {
        const char* srcH = (const char*)g_B3hi + q0 * 16384;
        for (int i = tid; i < 1024; i += 256) {
            int row = i >> 3, u = i & 7;
            uint32_t doff = (uint32_t)(row * 128 + ((u ^ (row & 7)) << 4));
            int soff = (row * 64 + u * 8) * 2;
            cp16(sb + OFF_B0 + doff, srcH + soff);
        }
        CP_COMMIT();
    }
    {
        int c = tid >> 1, off = (tid & 1) * 8;
        const float4* xp = (const float4*)(x + (b * NC + c) * L + off);
        float4 v0 = xp[0], v1 = xp[1];
        float* dst = Xs + c * 17 + off;
        dst[0] = v0.x; dst[1] = v0.y; dst[2] = v0.z; dst[3] = v0.w;
        dst[4] = v1.x; dst[5] = v1.y; dst[6] = v1.z; dst[7] = v1.w;
    }
    for (int i = tid; i < NT3; i += 256) sIdx[i] = g_idx3[i];
    __syncthreads();                       // Xs/idx ready for build

    // build A(q0) -> A0
    for (int item = tid; item < 1024; item += 256) {
        int c = item & 127, u = item >> 7;
        const float* Xc = Xs + c * 17;
        float m[8];
#pragma unroll
        for (int e = 0; e < 8; e++) {
            int gt = q0 * 64 + u * 8 + e;
            if (gt < NT3) {
                unsigned uu = sIdx[gt];
                m[e] = Xc[uu & 255] * Xc[(uu >> 8) & 255] * Xc[(uu >> 16) & 255];
            } else m[e] = 0.f;
        }
        uint32_t h[4];
#pragma unroll
        for (int p = 0; p < 4; p++) {
            __half2 hp = __floats2half2_rn(m[2 * p], m[2 * p + 1]);
            h[p] = *(uint32_t*)&hp;
        }
        uint32_t doff = (uint32_t)(c * 128 + ((u ^ (c & 7)) << 4));
        *(uint4*)(smc + OFF_A0 + doff) = make_uint4(h[0], h[1], h[2], h[3]);
    }
    CP_WAIT0();
    __syncthreads();                       // A(q0) + B(q0) visible to all

    float acc[16][4];
#pragma unroll
    for (int nt = 0; nt < 16; nt++)
#pragma unroll
        for (int k = 0; k < 4; k++) acc[nt][k] = 0.f;

    const int rw = wid & 3, cw = wid >> 2;
    const int R0 = rw * 32, C0 = cw * 64;
    const int mat = lane >> 3, lr = lane & 7;
    const int g = lane >> 2;

    for (int i = 0, q = q0; q < q1; ++i, ++q) {
        const uint32_t bufA = (i & 1) ? OFF_A1 : OFF_A0;
        const uint32_t bufAn = (i & 1) ? OFF_A0 : OFF_A1;
        const uint32_t bufB = (i & 1) ? OFF_B1 : OFF_B0;
        const uint32_t bufBn = (i & 1) ? OFF_B0 : OFF_B1;

        if (q + 1 < q1) {
            // stream B(q+1) into alternate buffer
            const char* srcH = (const char*)g_B3hi + (q + 1) * 16384;
            for (int ii = tid; ii < 1024; ii += 256) {
                int row = ii >> 3, u = ii & 7;
                uint32_t doff = (uint32_t)(row * 128 + ((u ^ (row & 7)) << 4));
                int soff = (row * 64 + u * 8) * 2;
                cp16(sb + bufBn + doff, srcH + soff);
            }
            CP_COMMIT();
            // build A(q+1) into alternate buffer -- overlaps MMA(q)
            for (int item = tid; item < 1024; item += 256) {
                int c = item & 127, u = item >> 7;
                const float* Xc = Xs + c * 17;
                float m[8];
#pragma unroll
                for (int e = 0; e < 8; e++) {
                    int gt = (q + 1) * 64 + u * 8 + e;
                    if (gt < NT3) {
                        unsigned uu = sIdx[gt];
                        m[e] = Xc[uu & 255] * Xc[(uu >> 8) & 255] * Xc[(uu >> 16) & 255];
                    } else m[e] = 0.f;
                }
                uint32_t h[4];
#pragma unroll
                for (int p = 0; p < 4; p++) {
                    __half2 hp = __floats2half2_rn(m[2 * p], m[2 * p + 1]);
                    h[p] = *(uint32_t*)&hp;
                }
                uint32_t doff = (uint32_t)(c * 128 + ((u ^ (c & 7)) << 4));
                *(uint4*)(smc + bufAn + doff) = make_uint4(h[0], h[1], h[2], h[3]);
            }
        }

        // MMA(q): 4 k-steps; warp tile 32 rows x 64 cols; single fp16 term
#pragma unroll
        for (int s = 0; s < 4; s++) {
            const int u0 = s * 2;
            uint32_t ah0[4], ah1[4];
            {
                int arow = R0 + lr + (mat & 1) * 8;
                int au = u0 + (mat >> 1);
                ldsm4(ah0, sb + bufA + (uint32_t)(arow * 128 + ((au ^ (arow & 7)) << 4)));
                int arow1 = arow + 16;
                ldsm4(ah1, sb + bufA + (uint32_t)(arow1 * 128 + ((au ^ (arow1 & 7)) << 4)));
            }
#pragma unroll
            for (int p = 0; p < 4; p++) {
                int brow = C0 + p * 16 + (mat >> 1) * 8 + lr;
                int bu = u0 + (mat & 1);
                uint32_t boff = (uint32_t)(brow * 128 + ((bu ^ (brow & 7)) << 4));
                uint32_t bh[4];
                ldsm4(bh, sb + bufB + boff);
                mma16816h(acc[p * 2],         ah0, bh[0], bh[1]);
                mma16816h(acc[p * 2 + 1],     ah0, bh[2], bh[3]);
                mma16816h(acc[8 + p * 2],     ah1, bh[0], bh[1]);
                mma16816h(acc[8 + p * 2 + 1], ah1, bh[2], bh[3]);
            }
        }
        CP_WAIT0();        // B(q+1) landed (own thread's copies)
        __syncthreads();   // A(q+1)/B(q+1) ready; MMA(q) done reading buffers
    }

    // ===== epilogue: weight by wy, reduce cols (shfl) + col-groups (smem) ====
    float* red = (float*)(smc + OFF_A0);   // alias A0 (free after loop + sync)
    const float* wyb = g_wy + b * NWY * NC;
    float ct[4][4];
#pragma unroll
    for (int a = 0; a < 4; a++)
#pragma unroll
        for (int t = 0; t < 4; t++) ct[a][t] = 0.f;
#pragma unroll
    for (int mi = 0; mi < 2; mi++) {
        int ra = R0 + mi * 16 + g;
        int rb = ra + 8;
#pragma unroll
        for (int ni = 0; ni < 8; ni++) {
#pragma unroll
            for (int hh = 0; hh < 2; hh++) {
                int j = C0 + ni * 8 + 2 * (lane & 3) + hh;
                if (j < 122) {
                    int tgt, wyc;
                    if (j < 23) { tgt = 0; wyc = j; }
                    else { int wq = (j - 23) / 33; tgt = 1 + wq; wyc = 23 + (j - 23 - wq * 33); }
                    ct[mi * 2 + 0][tgt] += acc[mi * 8 + ni][hh]     * wyb[wyc * NC + ra];
                    ct[mi * 2 + 1][tgt] += acc[mi * 8 + ni][2 + hh] * wyb[wyc * NC + rb];
                }
            }
        }
    }
#pragma unroll
    for (int a = 0; a < 4; a++)
#pragma unroll
        for (int t = 0; t < 4; t++) {
            ct[a][t] += __shfl_xor_sync(0xffffffffu, ct[a][t], 1);
            ct[a][t] += __shfl_xor_sync(0xffffffffu, ct[a][t], 2);
        }
    if ((lane & 3) == 0) {
#pragma unroll
        for (int mi = 0; mi < 2; mi++) {
            int ra = R0 + mi * 16 + g;
#pragma unroll
            for (int t = 0; t < 4; t++) {
                red[(cw * 128 + ra) * 4 + t]     = ct[mi * 2 + 0][t];
                red[(cw * 128 + ra + 8) * 4 + t] = ct[mi * 2 + 1][t];
            }
        }
    }
    __syncthreads();
    for (int i = tid; i < 512; i += 256) {
        int row = i >> 2, tgt = i & 3;
        float v = red[row * 4 + tgt] + red[(128 + row) * 4 + tgt];
        float* ob = out + b * 512;
        if (tgt == 0) atomicAdd(&ob[row], v);
        else atomicAdd(&ob[128 + 3 * row + (tgt - 1)], v);
    }
}

extern "C" void kernel_launch(void* const* d_in, const int* in_sizes, int n_in,
                              void* d_out, int out_size) {
    const float* x      = (const float*)d_in[0];
    const float* y      = (const float*)d_in[1];
    const float* U1_0e  = (const float*)d_in[2];
    const float* U2_0e  = (const float*)d_in[3];
    const float* U3_0e  = (const float*)d_in[4];
    const float* U1_1o  = (const float*)d_in[5];
    const float* U2_1o  = (const float*)d_in[6];
    const float* U3_1o  = (const float*)d_in[7];
    const float* w1_0e  = (const float*)d_in[8];
    const float* w2_0e  = (const float*)d_in[9];
    const float* w3_0e  = (const float*)d_in[10];
    const float* w1_1o  = (const float*)d_in[11];
    const float* w2_1o  = (const float*)d_in[12];
    const float* w3_1o  = (const float*)d_in[13];
    float* out = (float*)d_out;

    cudaFuncSetAttribute(k_main, cudaFuncAttributeMaxDynamicSharedMemorySize, SMEM_TOTAL);

    k_setup<<<NT3P + NT2 + 1, 128>>>(U1_0e, U2_0e, U3_0e, U1_1o, U2_1o, U3_1o);
    k_wy<<<NB, 256>>>(y, x, w3_0e, w3_1o, w2_0e, w2_1o, w1_0e, w1_1o, out);
    k_main<<<2 * NB, 256, SMEM_TOTAL>>>(x, out);
}